// round 2
// baseline (speedup 1.0000x reference)
#include <cuda_runtime.h>
#include <cuda_bf16.h>
#include <stdint.h>

#define DIM_  2048
#define HID_  2048
#define NH_   4
#define HD_   512
#define B_    4
#define L_    2048
#define NTOK_ 8192
#define GN_   8192
#define EPS_  1e-6f
#define CH_   64
#define NCH_  32
#define BH_   16
#define BHD_  (BH_*HD_)

// ---------------- device scratch ----------------
__device__ __nv_bfloat16 g_x_hi[NTOK_*DIM_],  g_x_lo[NTOK_*DIM_];
__device__ __nv_bfloat16 g_Win_hi[HID_*DIM_], g_Win_lo[HID_*DIM_];
__device__ __nv_bfloat16 g_Wg_hi[(size_t)GN_*HID_], g_Wg_lo[(size_t)GN_*HID_];
__device__ __nv_bfloat16 g_Wo_hi[DIM_*HID_],  g_Wo_lo[DIM_*HID_];
__device__ __nv_bfloat16 g_xp_hi[NTOK_*HID_], g_xp_lo[NTOK_*HID_];
__device__ float         g_gates[(size_t)NTOK_*GN_];
__device__ __nv_bfloat16 g_h_hi[NTOK_*HID_],  g_h_lo[NTOK_*HID_];
__device__ float g_scanA[NCH_*BHD_], g_scanB[NCH_*BHD_], g_carry[NCH_*BHD_];

// ---------------- helpers ----------------
__device__ __forceinline__ uint32_t smem_u32(const void* p){
    uint32_t a;
    asm("{ .reg .u64 t; cvta.to.shared.u64 t, %1; cvt.u32.u64 %0, t; }" : "=r"(a) : "l"(p));
    return a;
}
__device__ __forceinline__ void cp16(uint32_t d, const void* s){
    asm volatile("cp.async.cg.shared.global [%0], [%1], 16;" :: "r"(d), "l"(s) : "memory");
}
__device__ __forceinline__ void cp_commit(){ asm volatile("cp.async.commit_group;" ::: "memory"); }
template <int N> __device__ __forceinline__ void cp_wait(){ asm volatile("cp.async.wait_group %0;" :: "n"(N) : "memory"); }

__device__ __forceinline__ void ldsm4(uint32_t& r0, uint32_t& r1, uint32_t& r2, uint32_t& r3, uint32_t a){
    asm volatile("ldmatrix.sync.aligned.m8n8.x4.shared.b16 {%0,%1,%2,%3}, [%4];"
        : "=r"(r0), "=r"(r1), "=r"(r2), "=r"(r3) : "r"(a));
}
__device__ __forceinline__ void mma16816(float* d, const uint32_t* a, const uint32_t* b){
    asm volatile("mma.sync.aligned.m16n8k16.row.col.f32.bf16.bf16.f32 "
        "{%0,%1,%2,%3},{%4,%5,%6,%7},{%8,%9},{%0,%1,%2,%3};"
        : "+f"(d[0]), "+f"(d[1]), "+f"(d[2]), "+f"(d[3])
        : "r"(a[0]), "r"(a[1]), "r"(a[2]), "r"(a[3]), "r"(b[0]), "r"(b[1]));
}
__device__ __forceinline__ float sigmoidf_(float x){ return 1.f/(1.f + expf(-x)); }

// ---------------- split fp32 -> (hi, lo) bf16 ----------------
__global__ void split_kernel(const float* __restrict__ src,
                             __nv_bfloat16* __restrict__ hi,
                             __nv_bfloat16* __restrict__ lo, int n4){
    int i = blockIdx.x*blockDim.x + threadIdx.x;
    if (i >= n4) return;
    float4 v = ((const float4*)src)[i];
    __nv_bfloat16 h0 = __float2bfloat16(v.x), h1 = __float2bfloat16(v.y);
    __nv_bfloat16 h2 = __float2bfloat16(v.z), h3 = __float2bfloat16(v.w);
    __nv_bfloat16 l0 = __float2bfloat16(v.x - __bfloat162float(h0));
    __nv_bfloat16 l1 = __float2bfloat16(v.y - __bfloat162float(h1));
    __nv_bfloat16 l2 = __float2bfloat16(v.z - __bfloat162float(h2));
    __nv_bfloat16 l3 = __float2bfloat16(v.w - __bfloat162float(h3));
    __nv_bfloat162* H = (__nv_bfloat162*)hi;
    __nv_bfloat162* L = (__nv_bfloat162*)lo;
    H[2*i]   = __nv_bfloat162{h0, h1};  H[2*i+1] = __nv_bfloat162{h2, h3};
    L[2*i]   = __nv_bfloat162{l0, l1};  L[2*i+1] = __nv_bfloat162{l2, l3};
}

// ---------------- bf16x3 GEMM: C[M,N] = A[M,K] * B[N,K]^T (+bias) ----------------
#define BM 128
#define BN 128
#define BK 32
#define STG 3
#define SSTR 40          // padded row stride in bf16 elems
#define TPB 256
#define STAGE_E (128*SSTR)
#define SMEMSZ (4*STG*STAGE_E*2)

__global__ void __launch_bounds__(TPB, 1) gemm_bf16x3(
    const __nv_bfloat16* __restrict__ Ah, const __nv_bfloat16* __restrict__ Al,
    const __nv_bfloat16* __restrict__ Bh, const __nv_bfloat16* __restrict__ Bl,
    const float* __restrict__ bias, float* __restrict__ C,
    __nv_bfloat16* __restrict__ Ch, __nv_bfloat16* __restrict__ Cl,
    int M, int N, int K)
{
    extern __shared__ __nv_bfloat16 sm[];
    __nv_bfloat16* sAh = sm;
    __nv_bfloat16* sAl = sAh + STG*STAGE_E;
    __nv_bfloat16* sBh = sAl + STG*STAGE_E;
    __nv_bfloat16* sBl = sBh + STG*STAGE_E;
    uint32_t uAh = smem_u32(sAh), uAl = smem_u32(sAl);
    uint32_t uBh = smem_u32(sBh), uBl = smem_u32(sBl);

    const int tid = threadIdx.x;
    const int bm = blockIdx.y, bn = blockIdx.x;
    const int KT = K / BK;

    auto load_stage = [&](int kt, int st){
        #pragma unroll
        for (int j = 0; j < 2; j++){
            int lin = tid + j*TPB;                // 0..511
            int r = lin >> 2, c = (lin & 3) * 8;
            const __nv_bfloat16* gA = Ah + (size_t)(bm*BM + r)*K + kt*BK + c;
            const __nv_bfloat16* gAl2 = Al + (size_t)(bm*BM + r)*K + kt*BK + c;
            const __nv_bfloat16* gB = Bh + (size_t)(bn*BN + r)*K + kt*BK + c;
            const __nv_bfloat16* gBl2 = Bl + (size_t)(bn*BN + r)*K + kt*BK + c;
            uint32_t so = (uint32_t)(((st*128 + r)*SSTR + c) * 2);
            cp16(uAh + so, gA);  cp16(uAl + so, gAl2);
            cp16(uBh + so, gB);  cp16(uBl + so, gBl2);
        }
    };

    load_stage(0, 0); cp_commit();
    load_stage(1, 1); cp_commit();

    const int warp = tid >> 5, ln = tid & 31;
    const int wm = warp >> 1, wn = warp & 1;

    float acc[2][8][4];
    #pragma unroll
    for (int a = 0; a < 2; a++)
        #pragma unroll
        for (int b = 0; b < 8; b++)
            #pragma unroll
            for (int q = 0; q < 4; q++) acc[a][b][q] = 0.f;

    for (int kt = 0; kt < KT; kt++){
        cp_wait<1>();
        __syncthreads();
        if (kt + 2 < KT) load_stage(kt + 2, (kt + 2) % STG);
        cp_commit();
        const int st = kt % STG;

        #pragma unroll
        for (int ks = 0; ks < 2; ks++){
            uint32_t afh[2][4], afl[2][4];
            #pragma unroll
            for (int mt = 0; mt < 2; mt++){
                int mrow = wm*32 + mt*16 + ((ln >> 3) & 1)*8 + (ln & 7);
                int mcol = ks*16 + (ln >> 4)*8;
                uint32_t off = (uint32_t)(((st*128 + mrow)*SSTR + mcol) * 2);
                ldsm4(afh[mt][0], afh[mt][1], afh[mt][2], afh[mt][3], uAh + off);
                ldsm4(afl[mt][0], afl[mt][1], afl[mt][2], afl[mt][3], uAl + off);
            }
            uint32_t bfh[8][2], bfl[8][2];
            #pragma unroll
            for (int p = 0; p < 4; p++){
                int nrow = wn*64 + p*16 + (ln >> 4)*8 + (ln & 7);
                int ncol = ks*16 + ((ln >> 3) & 1)*8;
                uint32_t off = (uint32_t)(((st*128 + nrow)*SSTR + ncol) * 2);
                uint32_t r0, r1, r2, r3;
                ldsm4(r0, r1, r2, r3, uBh + off);
                bfh[2*p][0] = r0; bfh[2*p][1] = r1; bfh[2*p+1][0] = r2; bfh[2*p+1][1] = r3;
                ldsm4(r0, r1, r2, r3, uBl + off);
                bfl[2*p][0] = r0; bfl[2*p][1] = r1; bfl[2*p+1][0] = r2; bfl[2*p+1][1] = r3;
            }
            #pragma unroll
            for (int mt = 0; mt < 2; mt++)
                #pragma unroll
                for (int nt = 0; nt < 8; nt++){
                    mma16816(acc[mt][nt], afh[mt], bfh[nt]);   // hi*hi
                    mma16816(acc[mt][nt], afh[mt], bfl[nt]);   // hi*lo
                    mma16816(acc[mt][nt], afl[mt], bfh[nt]);   // lo*hi
                }
        }
    }

    // epilogue
    const int orow = bm*BM + wm*32, ocol = bn*BN + wn*64;
    #pragma unroll
    for (int mt = 0; mt < 2; mt++)
        #pragma unroll
        for (int nt = 0; nt < 8; nt++){
            float* a = acc[mt][nt];
            int r0 = orow + mt*16 + (ln >> 2);
            int c0 = ocol + nt*8 + (ln & 3)*2;
            if (bias){
                float b0 = bias[c0], b1 = bias[c0+1];
                a[0] += b0; a[1] += b1; a[2] += b0; a[3] += b1;
            }
            if (C){
                *(float2*)(C + (size_t)r0*N + c0)     = float2{a[0], a[1]};
                *(float2*)(C + (size_t)(r0+8)*N + c0) = float2{a[2], a[3]};
            }
            if (Ch){
                #pragma unroll
                for (int q = 0; q < 2; q++){
                    size_t o = (size_t)(r0 + q*8)*N + c0;
                    __nv_bfloat16 h0 = __float2bfloat16(a[2*q]);
                    __nv_bfloat16 h1 = __float2bfloat16(a[2*q+1]);
                    *(__nv_bfloat162*)(Ch + o) = __nv_bfloat162{h0, h1};
                    *(__nv_bfloat162*)(Cl + o) = __nv_bfloat162{
                        __float2bfloat16(a[2*q]   - __bfloat162float(h0)),
                        __float2bfloat16(a[2*q+1] - __bfloat162float(h1))};
                }
            }
        }
}

// ---------------- scan pass 1: per-chunk (A = prod f, B) ----------------
__global__ void scan_pass1(){
    int blk = blockIdx.x;
    int ch = blk / BH_, bh = blk % BH_;
    int b = bh / NH_, h = bh % NH_;
    int d = threadIdx.x;
    float A = 1.f, Bv = 0.f;
    for (int s = 0; s < CH_; s++){
        int tok = b*L_ + ch*CH_ + s;
        size_t base = (size_t)tok*GN_ + h*(4*HD_) + d;
        float ig = g_gates[base], fg = g_gates[base + HD_], cg = g_gates[base + 3*HD_];
        float f = sigmoidf_(fg);
        Bv = f*Bv + expf(ig)*tanhf(cg);
        A *= f;
    }
    g_scanA[ch*BHD_ + bh*HD_ + d] = A;
    g_scanB[ch*BHD_ + bh*HD_ + d] = Bv;
}

// ---------------- scan pass 2: sequential chunk composition ----------------
__global__ void scan_pass2(){
    int idx = blockIdx.x*blockDim.x + threadIdx.x;  // 0..BHD_-1
    float c = 0.f;
    for (int ch = 0; ch < NCH_; ch++){
        g_carry[ch*BHD_ + idx] = c;
        c = g_scanA[ch*BHD_ + idx]*c + g_scanB[ch*BHD_ + idx];
    }
}

// ---------------- scan pass 3: replay + RMS norm + h ----------------
__global__ void scan_pass3(const float* __restrict__ rms_w){
    __shared__ float red[16];
    __shared__ float s_norm;
    int blk = blockIdx.x;
    int ch = blk / BH_, bh = blk % BH_;
    int b = bh / NH_, h = bh % NH_;
    int d = threadIdx.x;
    int warp = d >> 5, lane = d & 31;
    float c = g_carry[ch*BHD_ + bh*HD_ + d];
    float w = rms_w[d];
    for (int s = 0; s < CH_; s++){
        int tok = b*L_ + ch*CH_ + s;
        size_t base = (size_t)tok*GN_ + h*(4*HD_) + d;
        float ig = g_gates[base],        fg = g_gates[base + HD_];
        float og = g_gates[base + 2*HD_], cg = g_gates[base + 3*HD_];
        c = sigmoidf_(fg)*c + expf(ig)*tanhf(cg);
        float sq = c*c;
        #pragma unroll
        for (int o = 16; o; o >>= 1) sq += __shfl_xor_sync(0xffffffffu, sq, o);
        if (!lane) red[warp] = sq;
        __syncthreads();
        if (warp == 0){
            float v = (lane < 16) ? red[lane] : 0.f;
            #pragma unroll
            for (int o = 8; o; o >>= 1) v += __shfl_xor_sync(0xffffffffu, v, o);
            if (!lane) s_norm = rsqrtf(v*(1.f/HD_) + EPS_);
        }
        __syncthreads();
        float cn = c * s_norm * w;
        float hv = sigmoidf_(og) * tanhf(cn);
        size_t ho = (size_t)tok*HID_ + h*HD_ + d;
        __nv_bfloat16 hh = __float2bfloat16(hv);
        g_h_hi[ho] = hh;
        g_h_lo[ho] = __float2bfloat16(hv - __bfloat162float(hh));
    }
}

// ---------------- launch ----------------
extern "C" void kernel_launch(void* const* d_in, const int* in_sizes, int n_in,
                              void* d_out, int out_size){
    const float* x      = (const float*)d_in[0];
    const float* W_in   = (const float*)d_in[1];
    const float* W_gate = (const float*)d_in[2];
    const float* b_gate = (const float*)d_in[3];
    const float* rms_w  = (const float*)d_in[4];
    const float* W_out  = (const float*)d_in[5];

    void *xh, *xl, *wih, *wil, *wgh, *wgl, *woh, *wol, *xph, *xpl, *gts, *hh, *hl;
    cudaGetSymbolAddress(&xh,  g_x_hi);   cudaGetSymbolAddress(&xl,  g_x_lo);
    cudaGetSymbolAddress(&wih, g_Win_hi); cudaGetSymbolAddress(&wil, g_Win_lo);
    cudaGetSymbolAddress(&wgh, g_Wg_hi);  cudaGetSymbolAddress(&wgl, g_Wg_lo);
    cudaGetSymbolAddress(&woh, g_Wo_hi);  cudaGetSymbolAddress(&wol, g_Wo_lo);
    cudaGetSymbolAddress(&xph, g_xp_hi);  cudaGetSymbolAddress(&xpl, g_xp_lo);
    cudaGetSymbolAddress(&gts, g_gates);
    cudaGetSymbolAddress(&hh,  g_h_hi);   cudaGetSymbolAddress(&hl,  g_h_lo);

    cudaFuncSetAttribute(gemm_bf16x3, cudaFuncAttributeMaxDynamicSharedMemorySize, SMEMSZ);

    // split inputs into hi/lo bf16
    int n4;
    n4 = NTOK_*DIM_/4; split_kernel<<<(n4+255)/256, 256>>>(x, (__nv_bfloat16*)xh, (__nv_bfloat16*)xl, n4);
    n4 = HID_*DIM_/4;  split_kernel<<<(n4+255)/256, 256>>>(W_in, (__nv_bfloat16*)wih, (__nv_bfloat16*)wil, n4);
    n4 = GN_*HID_/4;   split_kernel<<<(n4+255)/256, 256>>>(W_gate, (__nv_bfloat16*)wgh, (__nv_bfloat16*)wgl, n4);
    n4 = DIM_*HID_/4;  split_kernel<<<(n4+255)/256, 256>>>(W_out, (__nv_bfloat16*)woh, (__nv_bfloat16*)wol, n4);

    // G1: xp = x @ W_in^T   (write split only)
    gemm_bf16x3<<<dim3(HID_/BN, NTOK_/BM), TPB, SMEMSZ>>>(
        (const __nv_bfloat16*)xh, (const __nv_bfloat16*)xl,
        (const __nv_bfloat16*)wih, (const __nv_bfloat16*)wil,
        nullptr, nullptr, (__nv_bfloat16*)xph, (__nv_bfloat16*)xpl,
        NTOK_, HID_, DIM_);

    // G2: gates = xp @ W_gate^T + b_gate  (fp32 out)
    gemm_bf16x3<<<dim3(GN_/BN, NTOK_/BM), TPB, SMEMSZ>>>(
        (const __nv_bfloat16*)xph, (const __nv_bfloat16*)xpl,
        (const __nv_bfloat16*)wgh, (const __nv_bfloat16*)wgl,
        b_gate, (float*)gts, nullptr, nullptr,
        NTOK_, GN_, HID_);

    // chunked parallel scan
    scan_pass1<<<NCH_*BH_, HD_>>>();
    scan_pass2<<<BHD_/256, 256>>>();
    scan_pass3<<<NCH_*BH_, HD_>>>(rms_w);

    // G3: out = h @ W_out^T  (fp32 to d_out)
    gemm_bf16x3<<<dim3(DIM_/BN, NTOK_/BM), TPB, SMEMSZ>>>(
        (const __nv_bfloat16*)hh, (const __nv_bfloat16*)hl,
        (const __nv_bfloat16*)woh, (const __nv_bfloat16*)wol,
        nullptr, (float*)d_out, nullptr, nullptr,
        NTOK_, DIM_, HID_);
}